// round 14
// baseline (speedup 1.0000x reference)
#include <cuda_runtime.h>
#include <cuda_fp16.h>
#include <math.h>
#include <stdint.h>

// ---------------- problem constants ----------------
#define NE 40000
#define EPAD 40064          // 313 * 128
#define MTILES 313
#define NN 10000
#define NFULL 25
#define NM 19
#define MSG1_W 2432
#define H1_W 1216
#define RAD_W 1536
#define OUT_ELEMS (NN * NFULL * 64)

#define WSCALE 16.0f
#define WINV   0.0625f

// ---------------- static scratch ----------------
static __device__ float g_t64a[(size_t)NE * 64];
static __device__ float g_t64b[(size_t)NE * 64];
static __device__ float g_rad [(size_t)NE * RAD_W];
static __device__ float g_t576[(size_t)NE * 576];

static __device__ __half g_m1   [(size_t)EPAD * MSG1_W];
static __device__ __half g_h1   [(size_t)EPAD * H1_W];
static __device__ __half g_t64  [(size_t)EPAD * 64];
static __device__ __half g_msg2h[(size_t)NE * H1_W];

// CSR for node-major scatter
static __device__ int g_cnt[NN];
static __device__ int g_cur[NN];
static __device__ int g_off[NN + 1];
static __device__ int g_perm[NE];

// weight store: [Npad, K] transposed, hi/lo fp16 (scaled by WSCALE)
#define OFF_C1FC0 0          //  640 x  640
#define OFF_C1M1C 409600     //  512 x 1024 (complex-merged)
#define OFF_C1M2C 933888     //  384 x  768
#define OFF_C2FC0 1228800    //  384 x  320
#define OFF_C2M1C 1351680    //  512 x  512
#define OFF_C2M2C 1613824    //  384 x  384
#define OFF_RADW2 1761280    // 1536 x   64
#define WTOT      1859584
static __device__ __half g_wh[WTOT];
static __device__ __half g_wl[WTOT];

// ---------------- helpers ----------------
__device__ __forceinline__ float sigmoidf_(float x) { return 1.0f / (1.0f + expf(-x)); }
__device__ __forceinline__ float siluf_(float x)    { return x / (1.0f + expf(-x)); }
__device__ __forceinline__ float envf_(float dist) {
    float d = dist * (1.0f / 6.0f);
    float d2 = d * d;
    float d5 = d2 * d2 * d;
    return (d < 1.0f) ? (1.0f - 21.0f * d5 + 35.0f * d5 * d - 15.0f * d5 * d2) : 0.0f;
}

__device__ __forceinline__ uint32_t smem_u32(const void* p) {
    uint32_t a;
    asm("{ .reg .u64 t; cvta.to.shared.u64 t, %1; cvt.u32.u64 %0, t; }" : "=r"(a) : "l"(p));
    return a;
}
__device__ __forceinline__ void cpa16(uint32_t dst, const void* src) {
    asm volatile("cp.async.cg.shared.global [%0], [%1], 16;" :: "r"(dst), "l"(src));
}
__device__ __forceinline__ void ldsm4(uint32_t* r, uint32_t addr) {
    asm volatile("ldmatrix.sync.aligned.m8n8.x4.shared.b16 {%0,%1,%2,%3}, [%4];"
        : "=r"(r[0]), "=r"(r[1]), "=r"(r[2]), "=r"(r[3]) : "r"(addr));
}
__device__ __forceinline__ void mma16816(float* d, const uint32_t* a, const uint32_t* b) {
    asm volatile(
        "mma.sync.aligned.m16n8k16.row.col.f32.f16.f16.f32 "
        "{%0,%1,%2,%3}, {%4,%5,%6,%7}, {%8,%9}, {%0,%1,%2,%3};"
        : "+f"(d[0]), "+f"(d[1]), "+f"(d[2]), "+f"(d[3])
        : "r"(a[0]), "r"(a[1]), "r"(a[2]), "r"(a[3]), "r"(b[0]), "r"(b[1]));
}
__device__ __forceinline__ uint32_t pack2h(float a, float b) {
    __half2 h = __floats2half2_rn(a, b);
    return *(uint32_t*)&h;
}

// ---------------- pad rows [NE, EPAD) of fp16 A buffers ----------------
__global__ void pad_kernel() {
    int i = blockIdx.x * 256 + threadIdx.x;
    __half z = __float2half(0.0f);
    if (i < 64 * MSG1_W) {
        g_m1[(size_t)(NE + i / MSG1_W) * MSG1_W + (i % MSG1_W)] = z;
    }
    if (i < 64 * H1_W) {
        g_h1[(size_t)(NE + i / H1_W) * H1_W + (i % H1_W)] = z;
    }
    if (i < 64 * 64) {
        g_t64[(size_t)(NE + i / 64) * 64 + (i % 64)] = z;
    }
}

// ---------------- weight convert: all 7 matrices in one launch ----------------
__device__ __forceinline__ void cw_t(const float* __restrict__ W, int K, int N, int Npad,
                                     __half* hi, __half* lo, int i) {
    if (i < Npad * K) {
        int n = i / K, k = i - n * K;
        float v = (n < N) ? W[(size_t)k * N + n] * WSCALE : 0.0f;
        __half h = __float2half_rn(v);
        hi[i] = h;
        lo[i] = __float2half_rn(v - __half2float(h));
    }
}
__device__ __forceinline__ void cw_c(const float* __restrict__ W, int K2, int halfc,
                                     __half* hi, __half* lo, int i) {
    int Kc = 2 * K2, Nc = 2 * halfc;
    if (i < Nc * Kc) {
        int n = i / Kc, k = i - n * Kc;
        float v;
        if (k < K2)           v = W[(size_t)k * Nc + n];
        else if (n < halfc)   v = -W[(size_t)(k - K2) * Nc + halfc + n];
        else                  v = W[(size_t)(k - K2) * Nc + (n - halfc)];
        v *= WSCALE;
        __half h = __float2half_rn(v);
        hi[i] = h;
        lo[i] = __float2half_rn(v - __half2float(h));
    }
}
// block ranges: [0,1600) c1fc0 | [1600,3648) c1m1 | [3648,4800) c1m2 |
// [4800,5280) c2fc0 | [5280,6304) c2m1 | [6304,6880) c2m2 | [6880,7264) radw2
#define CONVW_BLOCKS 7264
__global__ void convw_all(
    const float* __restrict__ c1_fc0_w, const float* __restrict__ c1_m1_w,
    const float* __restrict__ c1_m2_w,  const float* __restrict__ c2_fc0_w,
    const float* __restrict__ c2_m1_w,  const float* __restrict__ c2_m2_w,
    const float* __restrict__ rad_w2)
{
    int b = blockIdx.x;
    int t = threadIdx.x;
    if (b < 1600)      cw_t(c1_fc0_w, 640, 576, 640,  g_wh + OFF_C1FC0, g_wl + OFF_C1FC0, (b - 0)    * 256 + t);
    else if (b < 3648) cw_c(c1_m1_w,  512, 256,       g_wh + OFF_C1M1C, g_wl + OFF_C1M1C, (b - 1600) * 256 + t);
    else if (b < 4800) cw_c(c1_m2_w,  384, 192,       g_wh + OFF_C1M2C, g_wl + OFF_C1M2C, (b - 3648) * 256 + t);
    else if (b < 5280) cw_t(c2_fc0_w, 320, 320, 384,  g_wh + OFF_C2FC0, g_wl + OFF_C2FC0, (b - 4800) * 256 + t);
    else if (b < 6304) cw_c(c2_m1_w,  256, 256,       g_wh + OFF_C2M1C, g_wl + OFF_C2M1C, (b - 5280) * 256 + t);
    else if (b < 6880) cw_c(c2_m2_w,  192, 192,       g_wh + OFF_C2M2C, g_wl + OFF_C2M2C, (b - 6304) * 256 + t);
    else               cw_t(rad_w2,   64, 1536, 1536, g_wh + OFF_RADW2, g_wl + OFF_RADW2, (b - 6880) * 256 + t);
}

// ---------------- SIMT fp32 GEMM (tiny radial layers only) ----------------
__global__ void __launch_bounds__(256) gemm64(
    const float* __restrict__ A, int lda,
    const float* __restrict__ W, int N, int K,
    const float* __restrict__ bias,
    float* __restrict__ C, int ldc)
{
    __shared__ __align__(16) float As[16][68];
    __shared__ __align__(16) float Bs[16][64];

    int tid = threadIdx.x;
    int tx = tid & 15, ty = tid >> 4;
    int m0 = blockIdx.y * 64, n0 = blockIdx.x * 64;
    int ar = tid >> 2, ac = (tid & 3) * 4;
    int wr = tid >> 4, wc = (tid & 15) * 4;
    const float* Ap = A + (size_t)(m0 + ar) * lda + ac;

    float acc[4][4];
#pragma unroll
    for (int i = 0; i < 4; i++)
#pragma unroll
        for (int j = 0; j < 4; j++) acc[i][j] = 0.0f;

    for (int k0 = 0; k0 < K; k0 += 16) {
        float4 av = *(const float4*)(Ap + k0);
        float4 bv = *(const float4*)(W + (size_t)(k0 + wr) * N + n0 + wc);
        As[ac + 0][ar] = av.x; As[ac + 1][ar] = av.y;
        As[ac + 2][ar] = av.z; As[ac + 3][ar] = av.w;
        *(float4*)&Bs[wr][wc] = bv;
        __syncthreads();
#pragma unroll
        for (int kk = 0; kk < 16; kk++) {
            float4 a = *(const float4*)&As[kk][ty * 4];
            float4 b = *(const float4*)&Bs[kk][tx * 4];
            float av_[4] = {a.x, a.y, a.z, a.w};
            float bv_[4] = {b.x, b.y, b.z, b.w};
#pragma unroll
            for (int i = 0; i < 4; i++)
#pragma unroll
                for (int j = 0; j < 4; j++) acc[i][j] += av_[i] * bv_[j];
        }
        __syncthreads();
    }
    float bb[4] = {0.f, 0.f, 0.f, 0.f};
    if (bias) {
#pragma unroll
        for (int j = 0; j < 4; j++) bb[j] = bias[n0 + tx * 4 + j];
    }
#pragma unroll
    for (int i = 0; i < 4; i++) {
        float* Cp = C + (size_t)(m0 + ty * 4 + i) * ldc + n0 + tx * 4;
#pragma unroll
        for (int j = 0; j < 4; j++) Cp[j] = acc[i][j] + bb[j];
    }
}

// ---------------- fp16 2-pass mma.sync GEMM, BM=128 BN=128 BK=32, 3-stage ----------------
// C = A @ (Wh+Wl)^T * WINV ; A fp16 single, W fp16 hi/lo scaled by WSCALE.
// modes: 0 = fp32 C (+bias), cols < Nreal
//        1 = conv1 gated fp16 -> h1 (mtype 1: rowbase 5 / 2: rowbase 13)
//        2 = conv2 envelope fp16 -> msg2h (mtype 0: cols<Nreal (+bias); 1/2: row remap)
#define STG_BYTES 30720     // A 128*40*2 + Bh 128*40*2 + Bl 128*40*2
#define NSTAGE 3
#define SMEM_MMA  (NSTAGE * STG_BYTES)

__global__ void __launch_bounds__(256) mma_gemm(
    const __half* __restrict__ A, int lda, int col0,
    const __half* __restrict__ Wh, const __half* __restrict__ Wl,
    int K, int mode, int mtype, int Nreal,
    const float* __restrict__ bias,
    const float* __restrict__ edge_distance,
    const float* __restrict__ gsrc,           // t576 for gating
    float* __restrict__ Cf, int ldc,
    __half* __restrict__ Ch)
{
    extern __shared__ __align__(128) char smem[];
    uint32_t sb = smem_u32(smem);
    int tid = threadIdx.x, lane = tid & 31, wid = tid >> 5;
    int wrow = wid & 1, wcol = wid >> 1;
    int m0 = blockIdx.y << 7, n0 = blockIdx.x << 7;
    int nch = K >> 5;

    float acc[4][4][4];
#pragma unroll
    for (int mt = 0; mt < 4; mt++)
#pragma unroll
        for (int nt = 0; nt < 4; nt++)
#pragma unroll
            for (int j = 0; j < 4; j++) acc[mt][nt][j] = 0.0f;

    auto load = [&](int s, int c) {
        int kc = c << 5;
        uint32_t so = sb + (uint32_t)s * STG_BYTES;
#pragma unroll
        for (int ii = 0; ii < 2; ii++) {
            int i = tid + ii * 256;                 // 0..511
            int row = i >> 2, ch = (i & 3) << 3;
            size_t gA = (size_t)(m0 + row) * lda + col0 + kc + ch;
            cpa16(so + (uint32_t)(row * 40 + ch) * 2, A + gA);
            size_t gB = (size_t)(n0 + row) * K + kc + ch;
            uint32_t d2 = so + 10240 + (uint32_t)(row * 40 + ch) * 2;
            cpa16(d2, Wh + gB);
            cpa16(d2 + 10240, Wl + gB);
        }
        asm volatile("cp.async.commit_group;" ::: "memory");
    };

    load(0, 0);
    if (nch > 1) load(1, 1);

    for (int c = 0; c < nch; c++) {
        int s = c % NSTAGE;
        if (c + 1 < nch) asm volatile("cp.async.wait_group 1;" ::: "memory");
        else             asm volatile("cp.async.wait_group 0;" ::: "memory");
        __syncthreads();
        if (c + 2 < nch) load((c + 2) % NSTAGE, c + 2);

        uint32_t so = sb + (uint32_t)s * STG_BYTES;
#pragma unroll
        for (int ks = 0; ks < 2; ks++) {
            uint32_t ah[4][4], bh[2][4], bl[2][4];
            int arow = wrow * 64 + (lane & 15);
            uint32_t aoff = so + (uint32_t)(arow * 40 + ks * 16 + ((lane >> 4) << 3)) * 2;
#pragma unroll
            for (int mt = 0; mt < 4; mt++)
                ldsm4(ah[mt], aoff + mt * 16 * 80);
            int nrow = wcol * 32 + (lane & 7) + ((lane >> 4) << 3);
            uint32_t boff = so + 10240 +
                            (uint32_t)(nrow * 40 + ks * 16 + (((lane >> 3) & 1) << 3)) * 2;
            ldsm4(bh[0], boff);
            ldsm4(bh[1], boff + 16 * 80);
            ldsm4(bl[0], boff + 10240);
            ldsm4(bl[1], boff + 10240 + 16 * 80);
#pragma unroll
            for (int mt = 0; mt < 4; mt++)
#pragma unroll
                for (int nt = 0; nt < 4; nt++) {
                    const uint32_t* bhp = &bh[nt >> 1][(nt & 1) * 2];
                    const uint32_t* blp = &bl[nt >> 1][(nt & 1) * 2];
                    mma16816(acc[mt][nt], ah[mt], bhp);
                    mma16816(acc[mt][nt], ah[mt], blp);
                }
        }
        __syncthreads();
    }

    // ---------------- fused epilogue (×WINV, vectorized stores) ----------------
    int mbase = m0 + wrow * 64;
    int ncb = n0 + wcol * 32 + (lane & 3) * 2;
#pragma unroll
    for (int mt = 0; mt < 4; mt++) {
#pragma unroll
        for (int half = 0; half < 2; half++) {
            int row = mbase + mt * 16 + (lane >> 2) + half * 8;
            if (row >= NE) continue;
            float env = 0.0f;
            if (mode == 2) env = envf_(edge_distance[row]);
#pragma unroll
            for (int nt = 0; nt < 4; nt++) {
                int ccol = ncb + nt * 8;
                float v0 = acc[mt][nt][half * 2 + 0] * WINV;
                float v1 = acc[mt][nt][half * 2 + 1] * WINV;
                if (mode == 0) {
                    if (ccol < Nreal) {
                        float b0 = 0.f, b1 = 0.f;
                        if (bias) { b0 = bias[ccol]; b1 = bias[ccol + 1]; }
                        float2* Cp = (float2*)(Cf + (size_t)row * ldc + ccol);
                        *Cp = make_float2(v0 + b0, v1 + b1);
                    }
                } else if (mode == 1) {
                    int j = ccol >> 6, cc = ccol & 63;
                    int hrow = ((mtype == 1) ? 5 : 13) + j;
                    int lp = (mtype == 1) ? (j & 3) : ((j < 3) ? j + 1 : j - 2);
                    float2 gv = *(const float2*)(gsrc + (size_t)row * 576 + 320 + lp * 64 + cc);
                    size_t o = (size_t)row * H1_W + hrow * 64 + cc;
                    *(uint32_t*)(Ch + o) = pack2h(v0 * sigmoidf_(gv.x), v1 * sigmoidf_(gv.y));
                } else {
                    int off;
                    float b0 = 0.f, b1 = 0.f;
                    if (mtype == 0) {
                        if (ccol >= Nreal) continue;
                        off = ccol;
                        if (bias) { b0 = bias[ccol]; b1 = bias[ccol + 1]; }
                    } else {
                        int j = ccol >> 6, cc = ccol & 63;
                        int hrow = ((mtype == 1) ? 5 : 13) + j;
                        off = hrow * 64 + cc;
                    }
                    size_t o = (size_t)row * H1_W + off;
                    *(uint32_t*)(Ch + o) = pack2h((v0 + b0) * env, (v1 + b1) * env);
                }
            }
        }
    }
}

// ---------------- LayerNorm + SiLU, 4 edges/block ----------------
__global__ void __launch_bounds__(256) lnsilu_kernel(
    float* __restrict__ h,
    const float* __restrict__ g,
    const float* __restrict__ b,
    __half* __restrict__ ho)
{
    int sub = threadIdx.x >> 6;
    int t = threadIdx.x & 63;
    int e = blockIdx.x * 4 + sub;
    float v = h[(size_t)e * 64 + t];

    __shared__ float red[4][4];
    float s = v;
#pragma unroll
    for (int o = 16; o > 0; o >>= 1) s += __shfl_xor_sync(0xffffffffu, s, o);
    if ((t & 31) == 0) red[sub][t >> 5] = s;
    __syncthreads();
    float mu = (red[sub][0] + red[sub][1]) * (1.0f / 64.0f);

    float d = v - mu;
    float s2 = d * d;
#pragma unroll
    for (int o = 16; o > 0; o >>= 1) s2 += __shfl_xor_sync(0xffffffffu, s2, o);
    if ((t & 31) == 0) red[sub][2 + (t >> 5)] = s2;
    __syncthreads();
    float var = (red[sub][2] + red[sub][3]) * (1.0f / 64.0f);

    float y = siluf_(d * rsqrtf(var + 1e-5f) * g[t] + b[t]);
    if (ho) ho[(size_t)e * 64 + t] = __float2half_rn(y);
    else    h[(size_t)e * 64 + t] = y;
}

// ---------------- wigner forward: register-blocked, fp16 out ----------------
__global__ void __launch_bounds__(128) wig_fwd2(
    const float* __restrict__ x,
    const int* __restrict__ edge_index,
    const float* __restrict__ wigner,
    const float* __restrict__ rad,
    __half* __restrict__ m1)
{
    int e = blockIdx.x;
    int tid = threadIdx.x;
    int w = tid >> 5, lane = tid & 31;
    __shared__ float sw[500];
    __shared__ __align__(16) float sx[NFULL * 128];

    int src = edge_index[e];
    int dst = edge_index[NE + e];
    const float* wp = wigner + (size_t)e * (NM * NFULL);
    for (int i = tid; i < NM * NFULL; i += 128) sw[i] = wp[i];

    const float4* xs = (const float4*)(x + (size_t)src * (NFULL * 64));
    const float4* xd = (const float4*)(x + (size_t)dst * (NFULL * 64));
    for (int i = tid; i < NFULL * 16; i += 128) {
        int k = i >> 4, c = (i & 15) << 2;
        *(float4*)&sx[k * 128 + c]      = xs[i];
        *(float4*)&sx[k * 128 + 64 + c] = xd[i];
    }
    __syncthreads();

    int r0 = w * 5;
    int nr = (w == 3) ? 4 : 5;
    int f0 = lane * 4;
    float acc[5][4];
#pragma unroll
    for (int i = 0; i < 5; i++)
#pragma unroll
        for (int j = 0; j < 4; j++) acc[i][j] = 0.0f;

#pragma unroll
    for (int k = 0; k < NFULL; k++) {
        float4 xv = *(const float4*)&sx[k * 128 + f0];
#pragma unroll
        for (int rr = 0; rr < 5; rr++) {
            float wv = sw[(r0 + rr) * NFULL + k];
            acc[rr][0] += wv * xv.x;
            acc[rr][1] += wv * xv.y;
            acc[rr][2] += wv * xv.z;
            acc[rr][3] += wv * xv.w;
        }
    }

    const float* rp = rad + (size_t)e * RAD_W;
    for (int rr = 0; rr < nr; rr++) {
        int r = r0 + rr;
        int sbase;
        if (r < 5)       sbase = r * 128;
        else if (r < 13) sbase = 640  + ((r - 5) & 3) * 128;
        else             sbase = 1152 + ((r - 13) % 3) * 128;
        size_t o = (size_t)e * MSG1_W + r * 128 + f0;
        float4 rv = *(const float4*)(rp + sbase + f0);
        uint2 pk;
        pk.x = pack2h(acc[rr][0] * rv.x, acc[rr][1] * rv.y);
        pk.y = pack2h(acc[rr][2] * rv.z, acc[rr][3] * rv.w);
        *(uint2*)(m1 + o) = pk;
    }
}

// ---------------- assemble conv1 rows 0..4 (silu + gated scalars) ----------------
__global__ void __launch_bounds__(128) assemble1a_kernel(
    const float* __restrict__ t576,
    __half* __restrict__ h1)
{
    int e = blockIdx.x;
    int tid = threadIdx.x;
    if (tid >= 80) return;
    const float* T = t576 + (size_t)e * 576;
    int o = tid * 4;
    int r = o >> 6, c = o & 63;
    float4 v = *(const float4*)(T + o);
    if (r == 0) {
        v.x = siluf_(v.x); v.y = siluf_(v.y); v.z = siluf_(v.z); v.w = siluf_(v.w);
    } else {
        float4 gv = *(const float4*)(T + 320 + (r - 1) * 64 + c);
        v.x *= sigmoidf_(gv.x); v.y *= sigmoidf_(gv.y);
        v.z *= sigmoidf_(gv.z); v.w *= sigmoidf_(gv.w);
    }
    uint2 pk;
    pk.x = pack2h(v.x, v.y);
    pk.y = pack2h(v.z, v.w);
    *(uint2*)(h1 + (size_t)e * H1_W + o) = pk;
}

// ---------------- CSR build (dst-sorted edge lists) ----------------
__global__ void csr_zero() {
    int i = blockIdx.x * 256 + threadIdx.x;
    if (i < NN) g_cnt[i] = 0;
}
__global__ void csr_hist(const int* __restrict__ edge_index) {
    int e = blockIdx.x * 256 + threadIdx.x;
    if (e < NE) atomicAdd(&g_cnt[edge_index[NE + e]], 1);
}
__global__ void __launch_bounds__(1024) csr_scan() {
    __shared__ int part[1024];
    int tid = threadIdx.x;
    int base = tid * 10;
    int loc[10];
    int s = 0;
#pragma unroll
    for (int i = 0; i < 10; i++) {
        int b = base + i;
        int v = (b < NN) ? g_cnt[b] : 0;
        loc[i] = v; s += v;
    }
    part[tid] = s;
    __syncthreads();
    for (int off = 1; off < 1024; off <<= 1) {
        int v = (tid >= off) ? part[tid - off] : 0;
        __syncthreads();
        part[tid] += v;
        __syncthreads();
    }
    int run = tid ? part[tid - 1] : 0;
#pragma unroll
    for (int i = 0; i < 10; i++) {
        int b = base + i;
        if (b < NN) { g_off[b] = run; g_cur[b] = run; run += loc[i]; }
    }
    if (tid == 1023) g_off[NN] = part[1023];
}
__global__ void csr_scatter(const int* __restrict__ edge_index) {
    int e = blockIdx.x * 256 + threadIdx.x;
    if (e < NE) {
        int dst = edge_index[NE + e];
        int pos = atomicAdd(&g_cur[dst], 1);
        g_perm[pos] = e;
    }
}

// ---------------- wigner inverse, node-major (no atomics) ----------------
__global__ void __launch_bounds__(256) wig_inv_node(
    const float* __restrict__ wigner_inv,
    const __half* __restrict__ msg2h,
    float* __restrict__ out)
{
    int n = blockIdx.x;
    int tid = threadIdx.x;
    int start = g_off[n], end = g_off[n + 1];

    float acc[7] = {0.f, 0.f, 0.f, 0.f, 0.f, 0.f, 0.f};
    __shared__ float sw[NFULL * NM];
    __shared__ __align__(16) float sm[NM * 64];

    for (int idx = start; idx < end; idx++) {
        int e = g_perm[idx];
        const float* wp = wigner_inv + (size_t)e * (NFULL * NM);
        for (int i = tid; i < NFULL * NM; i += 256) sw[i] = wp[i];
        const __half2* mp = (const __half2*)(msg2h + (size_t)e * H1_W);
        for (int i = tid; i < H1_W / 2; i += 256) {
            float2 f = __half22float2(mp[i]);
            sm[2 * i] = f.x;
            sm[2 * i + 1] = f.y;
        }
        __syncthreads();
#pragma unroll
        for (int k = 0; k < 7; k++) {
            int o = k * 256 + tid;
            if (o < NFULL * 64) {
                int j = o >> 6, c = o & 63;
                float s = 0.0f;
                const float* wr = &sw[j * NM];
#pragma unroll
                for (int r = 0; r < NM; r++) s += wr[r] * sm[r * 64 + c];
                acc[k] += s;
            }
        }
        __syncthreads();
    }

    float* op = out + (size_t)n * (NFULL * 64);
#pragma unroll
    for (int k = 0; k < 7; k++) {
        int o = k * 256 + tid;
        if (o < NFULL * 64) op[o] = acc[k];
    }
}

// ---------------- host side ----------------
static float* symaddrf(const void* sym) {
    void* p = nullptr;
    cudaGetSymbolAddress(&p, sym);
    return (float*)p;
}
static __half* symaddrh(const void* sym) {
    void* p = nullptr;
    cudaGetSymbolAddress(&p, sym);
    return (__half*)p;
}

extern "C" void kernel_launch(void* const* d_in, const int* in_sizes, int n_in,
                              void* d_out, int out_size)
{
    const float* x             = (const float*)d_in[0];
    const float* x_edge        = (const float*)d_in[1];
    const float* edge_distance = (const float*)d_in[2];
    const int*   edge_index    = (const int*)  d_in[3];
    const float* wigner        = (const float*)d_in[4];
    const float* wigner_inv    = (const float*)d_in[5];
    const float* rad_w0        = (const float*)d_in[6];
    const float* rad_b0        = (const float*)d_in[7];
    const float* rad_ln0_g     = (const float*)d_in[8];
    const float* rad_ln0_b     = (const float*)d_in[9];
    const float* rad_w1        = (const float*)d_in[10];
    const float* rad_b1        = (const float*)d_in[11];
    const float* rad_ln1_g     = (const float*)d_in[12];
    const float* rad_ln1_b     = (const float*)d_in[13];
    const float* rad_w2        = (const float*)d_in[14];
    const float* rad_b2        = (const float*)d_in[15];
    const float* c1_fc0_w      = (const float*)d_in[16];
    const float* c1_fc0_b      = (const float*)d_in[17];
    const float* c1_m1_w       = (const float*)d_in[18];
    const float* c1_m2_w       = (const float*)d_in[19];
    const float* c2_fc0_w      = (const float*)d_in[20];
    const float* c2_fc0_b      = (const float*)d_in[21];
    const float* c2_m1_w       = (const float*)d_in[22];
    const float* c2_m2_w       = (const float*)d_in[23];
    float* out = (float*)d_out;

    static int smem_set = 0;
    if (!smem_set) {
        cudaFuncSetAttribute(mma_gemm, cudaFuncAttributeMaxDynamicSharedMemorySize, SMEM_MMA);
        smem_set = 1;
    }

    float* p_t64a  = symaddrf(g_t64a);
    float* p_t64b  = symaddrf(g_t64b);
    float* p_rad   = symaddrf(g_rad);
    float* p_t576  = symaddrf(g_t576);
    __half* p_m1    = symaddrh(g_m1);
    __half* p_h1    = symaddrh(g_h1);
    __half* p_t64   = symaddrh(g_t64);
    __half* p_msg2h = symaddrh(g_msg2h);
    __half* p_wh    = symaddrh(g_wh);
    __half* p_wl    = symaddrh(g_wl);

    // 0. CSR build (independent of compute chain)
    csr_zero<<<(NN + 255) / 256, 256>>>();
    csr_hist<<<(NE + 255) / 256, 256>>>(edge_index);
    csr_scan<<<1, 1024>>>();
    csr_scatter<<<(NE + 255) / 256, 256>>>(edge_index);

    // 1. pad rows + weights
    pad_kernel<<<(64 * MSG1_W + 255) / 256, 256>>>();
    convw_all<<<CONVW_BLOCKS, 256>>>(c1_fc0_w, c1_m1_w, c1_m2_w,
                                     c2_fc0_w, c2_m1_w, c2_m2_w, rad_w2);

    // 2. radial MLP (layers 0/1 SIMT, layer 2 tensor)
    {
        dim3 grid(1, NE / 64);
        gemm64<<<grid, 256>>>(x_edge, 128, rad_w0, 64, 128, rad_b0, p_t64a, 64);
        lnsilu_kernel<<<NE / 4, 256>>>(p_t64a, rad_ln0_g, rad_ln0_b, nullptr);
        gemm64<<<grid, 256>>>(p_t64a, 64, rad_w1, 64, 64, rad_b1, p_t64b, 64);
        lnsilu_kernel<<<NE / 4, 256>>>(p_t64b, rad_ln1_g, rad_ln1_b, p_t64);
    }
    mma_gemm<<<dim3(12, MTILES), 256, SMEM_MMA>>>(
        p_t64, 64, 0, p_wh + OFF_RADW2, p_wl + OFF_RADW2, 64,
        0, 0, 1536, rad_b2, nullptr, nullptr, p_rad, RAD_W, nullptr);

    // 3. gather + wigner rotate + radial prescale -> fp16
    wig_fwd2<<<NE, 128>>>(x, edge_index, wigner, p_rad, p_m1);

    // 4. conv1: fc0 -> t576 (fp32), then gated complex m-convs -> h1 (fp16)
    mma_gemm<<<dim3(5, MTILES), 256, SMEM_MMA>>>(
        p_m1, MSG1_W, 0, p_wh + OFF_C1FC0, p_wl + OFF_C1FC0, 640,
        0, 0, 576, c1_fc0_b, nullptr, nullptr, p_t576, 576, nullptr);
    assemble1a_kernel<<<NE, 128>>>(p_t576, p_h1);
    mma_gemm<<<dim3(4, MTILES), 256, SMEM_MMA>>>(
        p_m1, MSG1_W, 640, p_wh + OFF_C1M1C, p_wl + OFF_C1M1C, 1024,
        1, 1, 512, nullptr, nullptr, p_t576, nullptr, 0, p_h1);
    mma_gemm<<<dim3(3, MTILES), 256, SMEM_MMA>>>(
        p_m1, MSG1_W, 1664, p_wh + OFF_C1M2C, p_wl + OFF_C1M2C, 768,
        1, 2, 384, nullptr, nullptr, p_t576, nullptr, 0, p_h1);

    // 5. conv2: envelope fused, write msg2h (fp16) directly
    mma_gemm<<<dim3(3, MTILES), 256, SMEM_MMA>>>(
        p_h1, H1_W, 0, p_wh + OFF_C2FC0, p_wl + OFF_C2FC0, 320,
        2, 0, 320, c2_fc0_b, edge_distance, nullptr, nullptr, 0, p_msg2h);
    mma_gemm<<<dim3(4, MTILES), 256, SMEM_MMA>>>(
        p_h1, H1_W, 320, p_wh + OFF_C2M1C, p_wl + OFF_C2M1C, 512,
        2, 1, 512, nullptr, edge_distance, nullptr, nullptr, 0, p_msg2h);
    mma_gemm<<<dim3(3, MTILES), 256, SMEM_MMA>>>(
        p_h1, H1_W, 832, p_wh + OFF_C2M2C, p_wl + OFF_C2M2C, 384,
        2, 2, 384, nullptr, edge_distance, nullptr, nullptr, 0, p_msg2h);

    // 6. inverse wigner, node-major accumulate (no atomics), writes ALL nodes
    wig_inv_node<<<NN, 256>>>(wigner_inv, p_msg2h, out);
}

// round 15
// speedup vs baseline: 1.0197x; 1.0197x over previous
#include <cuda_runtime.h>
#include <cuda_fp16.h>
#include <math.h>
#include <stdint.h>

// ---------------- problem constants ----------------
#define NE 40000
#define EPAD 40064          // 313 * 128
#define MTILES 313
#define NN 10000
#define NFULL 25
#define NM 19
#define MSG1_W 2432
#define H1_W 1216
#define RAD_W 1536
#define OUT_ELEMS (NN * NFULL * 64)

#define WSCALE 16.0f
#define WINV   0.0625f

// ---------------- static scratch ----------------
static __device__ float g_t64a[(size_t)NE * 64];
static __device__ float g_t64b[(size_t)NE * 64];
static __device__ float g_rad [(size_t)NE * RAD_W];
static __device__ float g_t576[(size_t)NE * 576];

static __device__ __half g_m1   [(size_t)EPAD * MSG1_W];
static __device__ __half g_h1   [(size_t)EPAD * H1_W];
static __device__ __half g_t64  [(size_t)EPAD * 64];
static __device__ __half g_msg2h[(size_t)NE * H1_W];

// weight store: [Npad, K] transposed, hi/lo fp16 (scaled by WSCALE)
#define OFF_C1FC0 0          //  640 x  640
#define OFF_C1M1C 409600     //  512 x 1024 (complex-merged)
#define OFF_C1M2C 933888     //  384 x  768
#define OFF_C2FC0 1228800    //  384 x  320
#define OFF_C2M1C 1351680    //  512 x  512
#define OFF_C2M2C 1613824    //  384 x  384
#define OFF_RADW2 1761280    // 1536 x   64
#define WTOT      1859584
static __device__ __half g_wh[WTOT];
static __device__ __half g_wl[WTOT];

// ---------------- helpers ----------------
__device__ __forceinline__ float sigmoidf_(float x) { return 1.0f / (1.0f + expf(-x)); }
__device__ __forceinline__ float siluf_(float x)    { return x / (1.0f + expf(-x)); }
__device__ __forceinline__ float envf_(float dist) {
    float d = dist * (1.0f / 6.0f);
    float d2 = d * d;
    float d5 = d2 * d2 * d;
    return (d < 1.0f) ? (1.0f - 21.0f * d5 + 35.0f * d5 * d - 15.0f * d5 * d2) : 0.0f;
}

__device__ __forceinline__ uint32_t smem_u32(const void* p) {
    uint32_t a;
    asm("{ .reg .u64 t; cvta.to.shared.u64 t, %1; cvt.u32.u64 %0, t; }" : "=r"(a) : "l"(p));
    return a;
}
__device__ __forceinline__ void cpa16(uint32_t dst, const void* src) {
    asm volatile("cp.async.cg.shared.global [%0], [%1], 16;" :: "r"(dst), "l"(src));
}
__device__ __forceinline__ void ldsm4(uint32_t* r, uint32_t addr) {
    asm volatile("ldmatrix.sync.aligned.m8n8.x4.shared.b16 {%0,%1,%2,%3}, [%4];"
        : "=r"(r[0]), "=r"(r[1]), "=r"(r[2]), "=r"(r[3]) : "r"(addr));
}
__device__ __forceinline__ void mma16816(float* d, const uint32_t* a, const uint32_t* b) {
    asm volatile(
        "mma.sync.aligned.m16n8k16.row.col.f32.f16.f16.f32 "
        "{%0,%1,%2,%3}, {%4,%5,%6,%7}, {%8,%9}, {%0,%1,%2,%3};"
        : "+f"(d[0]), "+f"(d[1]), "+f"(d[2]), "+f"(d[3])
        : "r"(a[0]), "r"(a[1]), "r"(a[2]), "r"(a[3]), "r"(b[0]), "r"(b[1]));
}
__device__ __forceinline__ uint32_t pack2h(float a, float b) {
    __half2 h = __floats2half2_rn(a, b);
    return *(uint32_t*)&h;
}
__device__ __forceinline__ void red4(float* p, float a, float b, float c, float d) {
    asm volatile("red.global.v4.f32.add [%0], {%1, %2, %3, %4};"
        :: "l"(p), "f"(a), "f"(b), "f"(c), "f"(d) : "memory");
}

// ---------------- zero fill ----------------
__global__ void zero_kernel(float* p, int n) {
    int i = blockIdx.x * blockDim.x + threadIdx.x;
    if (i < n) p[i] = 0.0f;
}

// ---------------- pad rows [NE, EPAD) of fp16 A buffers ----------------
__global__ void pad_kernel() {
    int i = blockIdx.x * 256 + threadIdx.x;
    __half z = __float2half(0.0f);
    if (i < 64 * MSG1_W) {
        g_m1[(size_t)(NE + i / MSG1_W) * MSG1_W + (i % MSG1_W)] = z;
    }
    if (i < 64 * H1_W) {
        g_h1[(size_t)(NE + i / H1_W) * H1_W + (i % H1_W)] = z;
    }
    if (i < 64 * 64) {
        g_t64[(size_t)(NE + i / 64) * 64 + (i % 64)] = z;
    }
}

// ---------------- weight convert: all 7 matrices in one launch ----------------
__device__ __forceinline__ void cw_t(const float* __restrict__ W, int K, int N, int Npad,
                                     __half* hi, __half* lo, int i) {
    if (i < Npad * K) {
        int n = i / K, k = i - n * K;
        float v = (n < N) ? W[(size_t)k * N + n] * WSCALE : 0.0f;
        __half h = __float2half_rn(v);
        hi[i] = h;
        lo[i] = __float2half_rn(v - __half2float(h));
    }
}
__device__ __forceinline__ void cw_c(const float* __restrict__ W, int K2, int halfc,
                                     __half* hi, __half* lo, int i) {
    int Kc = 2 * K2, Nc = 2 * halfc;
    if (i < Nc * Kc) {
        int n = i / Kc, k = i - n * Kc;
        float v;
        if (k < K2)           v = W[(size_t)k * Nc + n];
        else if (n < halfc)   v = -W[(size_t)(k - K2) * Nc + halfc + n];
        else                  v = W[(size_t)(k - K2) * Nc + (n - halfc)];
        v *= WSCALE;
        __half h = __float2half_rn(v);
        hi[i] = h;
        lo[i] = __float2half_rn(v - __half2float(h));
    }
}
// block ranges: [0,1600) c1fc0 | [1600,3648) c1m1 | [3648,4800) c1m2 |
// [4800,5280) c2fc0 | [5280,6304) c2m1 | [6304,6880) c2m2 | [6880,7264) radw2
#define CONVW_BLOCKS 7264
__global__ void convw_all(
    const float* __restrict__ c1_fc0_w, const float* __restrict__ c1_m1_w,
    const float* __restrict__ c1_m2_w,  const float* __restrict__ c2_fc0_w,
    const float* __restrict__ c2_m1_w,  const float* __restrict__ c2_m2_w,
    const float* __restrict__ rad_w2)
{
    int b = blockIdx.x;
    int t = threadIdx.x;
    if (b < 1600)      cw_t(c1_fc0_w, 640, 576, 640,  g_wh + OFF_C1FC0, g_wl + OFF_C1FC0, (b - 0)    * 256 + t);
    else if (b < 3648) cw_c(c1_m1_w,  512, 256,       g_wh + OFF_C1M1C, g_wl + OFF_C1M1C, (b - 1600) * 256 + t);
    else if (b < 4800) cw_c(c1_m2_w,  384, 192,       g_wh + OFF_C1M2C, g_wl + OFF_C1M2C, (b - 3648) * 256 + t);
    else if (b < 5280) cw_t(c2_fc0_w, 320, 320, 384,  g_wh + OFF_C2FC0, g_wl + OFF_C2FC0, (b - 4800) * 256 + t);
    else if (b < 6304) cw_c(c2_m1_w,  256, 256,       g_wh + OFF_C2M1C, g_wl + OFF_C2M1C, (b - 5280) * 256 + t);
    else if (b < 6880) cw_c(c2_m2_w,  192, 192,       g_wh + OFF_C2M2C, g_wl + OFF_C2M2C, (b - 6304) * 256 + t);
    else               cw_t(rad_w2,   64, 1536, 1536, g_wh + OFF_RADW2, g_wl + OFF_RADW2, (b - 6880) * 256 + t);
}

// ---------------- SIMT fp32 GEMM (tiny radial layers only) ----------------
__global__ void __launch_bounds__(256) gemm64(
    const float* __restrict__ A, int lda,
    const float* __restrict__ W, int N, int K,
    const float* __restrict__ bias,
    float* __restrict__ C, int ldc)
{
    __shared__ __align__(16) float As[16][68];
    __shared__ __align__(16) float Bs[16][64];

    int tid = threadIdx.x;
    int tx = tid & 15, ty = tid >> 4;
    int m0 = blockIdx.y * 64, n0 = blockIdx.x * 64;
    int ar = tid >> 2, ac = (tid & 3) * 4;
    int wr = tid >> 4, wc = (tid & 15) * 4;
    const float* Ap = A + (size_t)(m0 + ar) * lda + ac;

    float acc[4][4];
#pragma unroll
    for (int i = 0; i < 4; i++)
#pragma unroll
        for (int j = 0; j < 4; j++) acc[i][j] = 0.0f;

    for (int k0 = 0; k0 < K; k0 += 16) {
        float4 av = *(const float4*)(Ap + k0);
        float4 bv = *(const float4*)(W + (size_t)(k0 + wr) * N + n0 + wc);
        As[ac + 0][ar] = av.x; As[ac + 1][ar] = av.y;
        As[ac + 2][ar] = av.z; As[ac + 3][ar] = av.w;
        *(float4*)&Bs[wr][wc] = bv;
        __syncthreads();
#pragma unroll
        for (int kk = 0; kk < 16; kk++) {
            float4 a = *(const float4*)&As[kk][ty * 4];
            float4 b = *(const float4*)&Bs[kk][tx * 4];
            float av_[4] = {a.x, a.y, a.z, a.w};
            float bv_[4] = {b.x, b.y, b.z, b.w};
#pragma unroll
            for (int i = 0; i < 4; i++)
#pragma unroll
                for (int j = 0; j < 4; j++) acc[i][j] += av_[i] * bv_[j];
        }
        __syncthreads();
    }
    float bb[4] = {0.f, 0.f, 0.f, 0.f};
    if (bias) {
#pragma unroll
        for (int j = 0; j < 4; j++) bb[j] = bias[n0 + tx * 4 + j];
    }
#pragma unroll
    for (int i = 0; i < 4; i++) {
        float* Cp = C + (size_t)(m0 + ty * 4 + i) * ldc + n0 + tx * 4;
#pragma unroll
        for (int j = 0; j < 4; j++) Cp[j] = acc[i][j] + bb[j];
    }
}

// ---------------- fp16 2-pass mma.sync GEMM, BM=128 BN=128 BK=32, 3-stage ----------------
#define STG_BYTES 30720     // A 128*40*2 + Bh 128*40*2 + Bl 128*40*2
#define NSTAGE 3
#define SMEM_MMA  (NSTAGE * STG_BYTES)

__global__ void __launch_bounds__(256) mma_gemm(
    const __half* __restrict__ A, int lda, int col0,
    const __half* __restrict__ Wh, const __half* __restrict__ Wl,
    int K, int mode, int mtype, int Nreal,
    const float* __restrict__ bias,
    const float* __restrict__ edge_distance,
    const float* __restrict__ gsrc,           // t576 for gating
    float* __restrict__ Cf, int ldc,
    __half* __restrict__ Ch)
{
    extern __shared__ __align__(128) char smem[];
    uint32_t sb = smem_u32(smem);
    int tid = threadIdx.x, lane = tid & 31, wid = tid >> 5;
    int wrow = wid & 1, wcol = wid >> 1;
    int m0 = blockIdx.y << 7, n0 = blockIdx.x << 7;
    int nch = K >> 5;

    float acc[4][4][4];
#pragma unroll
    for (int mt = 0; mt < 4; mt++)
#pragma unroll
        for (int nt = 0; nt < 4; nt++)
#pragma unroll
            for (int j = 0; j < 4; j++) acc[mt][nt][j] = 0.0f;

    auto load = [&](int s, int c) {
        int kc = c << 5;
        uint32_t so = sb + (uint32_t)s * STG_BYTES;
#pragma unroll
        for (int ii = 0; ii < 2; ii++) {
            int i = tid + ii * 256;                 // 0..511
            int row = i >> 2, ch = (i & 3) << 3;
            size_t gA = (size_t)(m0 + row) * lda + col0 + kc + ch;
            cpa16(so + (uint32_t)(row * 40 + ch) * 2, A + gA);
            size_t gB = (size_t)(n0 + row) * K + kc + ch;
            uint32_t d2 = so + 10240 + (uint32_t)(row * 40 + ch) * 2;
            cpa16(d2, Wh + gB);
            cpa16(d2 + 10240, Wl + gB);
        }
        asm volatile("cp.async.commit_group;" ::: "memory");
    };

    load(0, 0);
    if (nch > 1) load(1, 1);

    for (int c = 0; c < nch; c++) {
        int s = c % NSTAGE;
        if (c + 1 < nch) asm volatile("cp.async.wait_group 1;" ::: "memory");
        else             asm volatile("cp.async.wait_group 0;" ::: "memory");
        __syncthreads();
        if (c + 2 < nch) load((c + 2) % NSTAGE, c + 2);

        uint32_t so = sb + (uint32_t)s * STG_BYTES;
#pragma unroll
        for (int ks = 0; ks < 2; ks++) {
            uint32_t ah[4][4], bh[2][4], bl[2][4];
            int arow = wrow * 64 + (lane & 15);
            uint32_t aoff = so + (uint32_t)(arow * 40 + ks * 16 + ((lane >> 4) << 3)) * 2;
#pragma unroll
            for (int mt = 0; mt < 4; mt++)
                ldsm4(ah[mt], aoff + mt * 16 * 80);
            int nrow = wcol * 32 + (lane & 7) + ((lane >> 4) << 3);
            uint32_t boff = so + 10240 +
                            (uint32_t)(nrow * 40 + ks * 16 + (((lane >> 3) & 1) << 3)) * 2;
            ldsm4(bh[0], boff);
            ldsm4(bh[1], boff + 16 * 80);
            ldsm4(bl[0], boff + 10240);
            ldsm4(bl[1], boff + 10240 + 16 * 80);
#pragma unroll
            for (int mt = 0; mt < 4; mt++)
#pragma unroll
                for (int nt = 0; nt < 4; nt++) {
                    const uint32_t* bhp = &bh[nt >> 1][(nt & 1) * 2];
                    const uint32_t* blp = &bl[nt >> 1][(nt & 1) * 2];
                    mma16816(acc[mt][nt], ah[mt], bhp);
                    mma16816(acc[mt][nt], ah[mt], blp);
                }
        }
        __syncthreads();
    }

    // ---------------- fused epilogue (×WINV, vectorized stores) ----------------
    int mbase = m0 + wrow * 64;
    int ncb = n0 + wcol * 32 + (lane & 3) * 2;
#pragma unroll
    for (int mt = 0; mt < 4; mt++) {
#pragma unroll
        for (int half = 0; half < 2; half++) {
            int row = mbase + mt * 16 + (lane >> 2) + half * 8;
            if (row >= NE) continue;
            float env = 0.0f;
            if (mode == 2) env = envf_(edge_distance[row]);
#pragma unroll
            for (int nt = 0; nt < 4; nt++) {
                int ccol = ncb + nt * 8;
                float v0 = acc[mt][nt][half * 2 + 0] * WINV;
                float v1 = acc[mt][nt][half * 2 + 1] * WINV;
                if (mode == 0) {
                    if (ccol < Nreal) {
                        float b0 = 0.f, b1 = 0.f;
                        if (bias) { b0 = bias[ccol]; b1 = bias[ccol + 1]; }
                        float2* Cp = (float2*)(Cf + (size_t)row * ldc + ccol);
                        *Cp = make_float2(v0 + b0, v1 + b1);
                    }
                } else if (mode == 1) {
                    int j = ccol >> 6, cc = ccol & 63;
                    int hrow = ((mtype == 1) ? 5 : 13) + j;
                    int lp = (mtype == 1) ? (j & 3) : ((j < 3) ? j + 1 : j - 2);
                    float2 gv = *(const float2*)(gsrc + (size_t)row * 576 + 320 + lp * 64 + cc);
                    size_t o = (size_t)row * H1_W + hrow * 64 + cc;
                    *(uint32_t*)(Ch + o) = pack2h(v0 * sigmoidf_(gv.x), v1 * sigmoidf_(gv.y));
                } else {
                    int off;
                    float b0 = 0.f, b1 = 0.f;
                    if (mtype == 0) {
                        if (ccol >= Nreal) continue;
                        off = ccol;
                        if (bias) { b0 = bias[ccol]; b1 = bias[ccol + 1]; }
                    } else {
                        int j = ccol >> 6, cc = ccol & 63;
                        int hrow = ((mtype == 1) ? 5 : 13) + j;
                        off = hrow * 64 + cc;
                    }
                    size_t o = (size_t)row * H1_W + off;
                    *(uint32_t*)(Ch + o) = pack2h((v0 + b0) * env, (v1 + b1) * env);
                }
            }
        }
    }
}

// ---------------- LayerNorm + SiLU, 4 edges/block ----------------
__global__ void __launch_bounds__(256) lnsilu_kernel(
    float* __restrict__ h,
    const float* __restrict__ g,
    const float* __restrict__ b,
    __half* __restrict__ ho)
{
    int sub = threadIdx.x >> 6;
    int t = threadIdx.x & 63;
    int e = blockIdx.x * 4 + sub;
    float v = h[(size_t)e * 64 + t];

    __shared__ float red[4][4];
    float s = v;
#pragma unroll
    for (int o = 16; o > 0; o >>= 1) s += __shfl_xor_sync(0xffffffffu, s, o);
    if ((t & 31) == 0) red[sub][t >> 5] = s;
    __syncthreads();
    float mu = (red[sub][0] + red[sub][1]) * (1.0f / 64.0f);

    float d = v - mu;
    float s2 = d * d;
#pragma unroll
    for (int o = 16; o > 0; o >>= 1) s2 += __shfl_xor_sync(0xffffffffu, s2, o);
    if ((t & 31) == 0) red[sub][2 + (t >> 5)] = s2;
    __syncthreads();
    float var = (red[sub][2] + red[sub][3]) * (1.0f / 64.0f);

    float y = siluf_(d * rsqrtf(var + 1e-5f) * g[t] + b[t]);
    if (ho) ho[(size_t)e * 64 + t] = __float2half_rn(y);
    else    h[(size_t)e * 64 + t] = y;
}

// ---------------- wigner forward: register-blocked, fp16 out ----------------
__global__ void __launch_bounds__(128) wig_fwd2(
    const float* __restrict__ x,
    const int* __restrict__ edge_index,
    const float* __restrict__ wigner,
    const float* __restrict__ rad,
    __half* __restrict__ m1)
{
    int e = blockIdx.x;
    int tid = threadIdx.x;
    int w = tid >> 5, lane = tid & 31;
    __shared__ float sw[500];
    __shared__ __align__(16) float sx[NFULL * 128];

    int src = edge_index[e];
    int dst = edge_index[NE + e];
    const float* wp = wigner + (size_t)e * (NM * NFULL);
    for (int i = tid; i < NM * NFULL; i += 128) sw[i] = wp[i];

    const float4* xs = (const float4*)(x + (size_t)src * (NFULL * 64));
    const float4* xd = (const float4*)(x + (size_t)dst * (NFULL * 64));
    for (int i = tid; i < NFULL * 16; i += 128) {
        int k = i >> 4, c = (i & 15) << 2;
        *(float4*)&sx[k * 128 + c]      = xs[i];
        *(float4*)&sx[k * 128 + 64 + c] = xd[i];
    }
    __syncthreads();

    int r0 = w * 5;
    int nr = (w == 3) ? 4 : 5;
    int f0 = lane * 4;
    float acc[5][4];
#pragma unroll
    for (int i = 0; i < 5; i++)
#pragma unroll
        for (int j = 0; j < 4; j++) acc[i][j] = 0.0f;

#pragma unroll
    for (int k = 0; k < NFULL; k++) {
        float4 xv = *(const float4*)&sx[k * 128 + f0];
#pragma unroll
        for (int rr = 0; rr < 5; rr++) {
            float wv = sw[(r0 + rr) * NFULL + k];
            acc[rr][0] += wv * xv.x;
            acc[rr][1] += wv * xv.y;
            acc[rr][2] += wv * xv.z;
            acc[rr][3] += wv * xv.w;
        }
    }

    const float* rp = rad + (size_t)e * RAD_W;
    for (int rr = 0; rr < nr; rr++) {
        int r = r0 + rr;
        int sbase;
        if (r < 5)       sbase = r * 128;
        else if (r < 13) sbase = 640  + ((r - 5) & 3) * 128;
        else             sbase = 1152 + ((r - 13) % 3) * 128;
        size_t o = (size_t)e * MSG1_W + r * 128 + f0;
        float4 rv = *(const float4*)(rp + sbase + f0);
        uint2 pk;
        pk.x = pack2h(acc[rr][0] * rv.x, acc[rr][1] * rv.y);
        pk.y = pack2h(acc[rr][2] * rv.z, acc[rr][3] * rv.w);
        *(uint2*)(m1 + o) = pk;
    }
}

// ---------------- assemble conv1 rows 0..4 (silu + gated scalars) ----------------
__global__ void __launch_bounds__(128) assemble1a_kernel(
    const float* __restrict__ t576,
    __half* __restrict__ h1)
{
    int e = blockIdx.x;
    int tid = threadIdx.x;
    if (tid >= 80) return;
    const float* T = t576 + (size_t)e * 576;
    int o = tid * 4;
    int r = o >> 6, c = o & 63;
    float4 v = *(const float4*)(T + o);
    if (r == 0) {
        v.x = siluf_(v.x); v.y = siluf_(v.y); v.z = siluf_(v.z); v.w = siluf_(v.w);
    } else {
        float4 gv = *(const float4*)(T + 320 + (r - 1) * 64 + c);
        v.x *= sigmoidf_(gv.x); v.y *= sigmoidf_(gv.y);
        v.z *= sigmoidf_(gv.z); v.w *= sigmoidf_(gv.w);
    }
    uint2 pk;
    pk.x = pack2h(v.x, v.y);
    pk.y = pack2h(v.z, v.w);
    *(uint2*)(h1 + (size_t)e * H1_W + o) = pk;
}

// ---------------- wigner inverse + vector red scatter ----------------
__global__ void __launch_bounds__(256) wig_inv_kernel(
    const float* __restrict__ wigner_inv,
    const __half* __restrict__ msg2h,
    const int* __restrict__ edge_index,
    float* __restrict__ out)
{
    int e = blockIdx.x;
    int tid = threadIdx.x;
    __shared__ float sw[NFULL * NM];
    __shared__ __align__(16) float sm[NM * 64];

    const float* wp = wigner_inv + (size_t)e * (NFULL * NM);
    for (int i = tid; i < NFULL * NM; i += 256) sw[i] = wp[i];
    const __half2* mp = (const __half2*)(msg2h + (size_t)e * H1_W);
    for (int i = tid; i < H1_W / 2; i += 256) {
        float2 f = __half22float2(mp[i]);
        sm[2 * i] = f.x;
        sm[2 * i + 1] = f.y;
    }
    __syncthreads();

    int dst = edge_index[NE + e];
    float* op = out + (size_t)dst * (NFULL * 64);
    for (int o4 = tid * 4; o4 < NFULL * 64; o4 += 1024) {
        int j = o4 >> 6, c = o4 & 63;
        const float* wr = &sw[j * NM];
        float s0 = 0.f, s1 = 0.f, s2 = 0.f, s3 = 0.f;
#pragma unroll
        for (int r = 0; r < NM; r++) {
            float w = wr[r];
            const float* smr = &sm[r * 64 + c];
            s0 += w * smr[0];
            s1 += w * smr[1];
            s2 += w * smr[2];
            s3 += w * smr[3];
        }
        red4(op + o4, s0, s1, s2, s3);
    }
}

// ---------------- host side ----------------
static float* symaddrf(const void* sym) {
    void* p = nullptr;
    cudaGetSymbolAddress(&p, sym);
    return (float*)p;
}
static __half* symaddrh(const void* sym) {
    void* p = nullptr;
    cudaGetSymbolAddress(&p, sym);
    return (__half*)p;
}

extern "C" void kernel_launch(void* const* d_in, const int* in_sizes, int n_in,
                              void* d_out, int out_size)
{
    const float* x             = (const float*)d_in[0];
    const float* x_edge        = (const float*)d_in[1];
    const float* edge_distance = (const float*)d_in[2];
    const int*   edge_index    = (const int*)  d_in[3];
    const float* wigner        = (const float*)d_in[4];
    const float* wigner_inv    = (const float*)d_in[5];
    const float* rad_w0        = (const float*)d_in[6];
    const float* rad_b0        = (const float*)d_in[7];
    const float* rad_ln0_g     = (const float*)d_in[8];
    const float* rad_ln0_b     = (const float*)d_in[9];
    const float* rad_w1        = (const float*)d_in[10];
    const float* rad_b1        = (const float*)d_in[11];
    const float* rad_ln1_g     = (const float*)d_in[12];
    const float* rad_ln1_b     = (const float*)d_in[13];
    const float* rad_w2        = (const float*)d_in[14];
    const float* rad_b2        = (const float*)d_in[15];
    const float* c1_fc0_w      = (const float*)d_in[16];
    const float* c1_fc0_b      = (const float*)d_in[17];
    const float* c1_m1_w       = (const float*)d_in[18];
    const float* c1_m2_w       = (const float*)d_in[19];
    const float* c2_fc0_w      = (const float*)d_in[20];
    const float* c2_fc0_b      = (const float*)d_in[21];
    const float* c2_m1_w       = (const float*)d_in[22];
    const float* c2_m2_w       = (const float*)d_in[23];
    float* out = (float*)d_out;

    static int smem_set = 0;
    if (!smem_set) {
        cudaFuncSetAttribute(mma_gemm, cudaFuncAttributeMaxDynamicSharedMemorySize, SMEM_MMA);
        smem_set = 1;
    }

    float* p_t64a  = symaddrf(g_t64a);
    float* p_t64b  = symaddrf(g_t64b);
    float* p_rad   = symaddrf(g_rad);
    float* p_t576  = symaddrf(g_t576);
    __half* p_m1    = symaddrh(g_m1);
    __half* p_h1    = symaddrh(g_h1);
    __half* p_t64   = symaddrh(g_t64);
    __half* p_msg2h = symaddrh(g_msg2h);
    __half* p_wh    = symaddrh(g_wh);
    __half* p_wl    = symaddrh(g_wl);

    // 0. zero output, pad rows, build weights
    zero_kernel<<<(OUT_ELEMS + 255) / 256, 256>>>(out, OUT_ELEMS);
    pad_kernel<<<(64 * MSG1_W + 255) / 256, 256>>>();
    convw_all<<<CONVW_BLOCKS, 256>>>(c1_fc0_w, c1_m1_w, c1_m2_w,
                                     c2_fc0_w, c2_m1_w, c2_m2_w, rad_w2);

    // 1. radial MLP (layers 0/1 SIMT, layer 2 tensor)
    {
        dim3 grid(1, NE / 64);
        gemm64<<<grid, 256>>>(x_edge, 128, rad_w0, 64, 128, rad_b0, p_t64a, 64);
        lnsilu_kernel<<<NE / 4, 256>>>(p_t64a, rad_ln0_g, rad_ln0_b, nullptr);
        gemm64<<<grid, 256>>>(p_t64a, 64, rad_w1, 64, 64, rad_b1, p_t64b, 64);
        lnsilu_kernel<<<NE / 4, 256>>>(p_t64b, rad_ln1_g, rad_ln1_b, p_t64);
    }
    mma_gemm<<<dim3(12, MTILES), 256, SMEM_MMA>>>(
        p_t64, 64, 0, p_wh + OFF_RADW2, p_wl + OFF_RADW2, 64,
        0, 0, 1536, rad_b2, nullptr, nullptr, p_rad, RAD_W, nullptr);

    // 2. gather + wigner rotate + radial prescale -> fp16
    wig_fwd2<<<NE, 128>>>(x, edge_index, wigner, p_rad, p_m1);

    // 3. conv1: fc0 -> t576 (fp32), then gated complex m-convs -> h1 (fp16)
    mma_gemm<<<dim3(5, MTILES), 256, SMEM_MMA>>>(
        p_m1, MSG1_W, 0, p_wh + OFF_C1FC0, p_wl + OFF_C1FC0, 640,
        0, 0, 576, c1_fc0_b, nullptr, nullptr, p_t576, 576, nullptr);
    assemble1a_kernel<<<NE, 128>>>(p_t576, p_h1);
    mma_gemm<<<dim3(4, MTILES), 256, SMEM_MMA>>>(
        p_m1, MSG1_W, 640, p_wh + OFF_C1M1C, p_wl + OFF_C1M1C, 1024,
        1, 1, 512, nullptr, nullptr, p_t576, nullptr, 0, p_h1);
    mma_gemm<<<dim3(3, MTILES), 256, SMEM_MMA>>>(
        p_m1, MSG1_W, 1664, p_wh + OFF_C1M2C, p_wl + OFF_C1M2C, 768,
        1, 2, 384, nullptr, nullptr, p_t576, nullptr, 0, p_h1);

    // 4. conv2: envelope fused, write msg2h (fp16) directly
    mma_gemm<<<dim3(3, MTILES), 256, SMEM_MMA>>>(
        p_h1, H1_W, 0, p_wh + OFF_C2FC0, p_wl + OFF_C2FC0, 320,
        2, 0, 320, c2_fc0_b, edge_distance, nullptr, nullptr, 0, p_msg2h);
    mma_gemm<<<dim3(4, MTILES), 256, SMEM_MMA>>>(
        p_h1, H1_W, 320, p_wh + OFF_C2M1C, p_wl + OFF_C2M1C, 512,
        2, 1, 512, nullptr, edge_distance, nullptr, nullptr, 0, p_msg2h);
    mma_gemm<<<dim3(3, MTILES), 256, SMEM_MMA>>>(
        p_h1, H1_W, 832, p_wh + OFF_C2M2C, p_wl + OFF_C2M2C, 384,
        2, 2, 384, nullptr, edge_distance, nullptr, nullptr, 0, p_msg2h);

    // 5. inverse wigner + vector-red scatter
    wig_inv_kernel<<<NE, 256>>>(wigner_inv, p_msg2h, edge_index, out);
}

// round 16
// speedup vs baseline: 1.2417x; 1.2178x over previous
#include <cuda_runtime.h>
#include <cuda_fp16.h>
#include <math.h>
#include <stdint.h>

// ---------------- problem constants ----------------
#define NE 40000
#define EPAD 40064          // 313 * 128
#define MTILES 313
#define NN 10000
#define NFULL 25
#define NM 19
#define MSG1_W 2432
#define H1_W 1216
#define RAD_W 1536
#define OUT_ELEMS (NN * NFULL * 64)

// ---------------- static scratch ----------------
static __device__ float g_t64a[(size_t)NE * 64];
static __device__ float g_t64b[(size_t)NE * 64];
static __device__ float g_rad [(size_t)NE * RAD_W];
static __device__ float g_t576[(size_t)NE * 576];

static __device__ __half g_m1   [(size_t)EPAD * MSG1_W];
static __device__ __half g_h1   [(size_t)EPAD * H1_W];
static __device__ __half g_t64  [(size_t)EPAD * 64];
static __device__ __half g_msg2h[(size_t)NE * H1_W];

// weight store: [Npad, K] transposed, single fp16
#define OFF_C1FC0 0          //  640 x  640
#define OFF_C1M1C 409600     //  512 x 1024 (complex-merged)
#define OFF_C1M2C 933888     //  384 x  768
#define OFF_C2FC0 1228800    //  384 x  320
#define OFF_C2M1C 1351680    //  512 x  512
#define OFF_C2M2C 1613824    //  384 x  384
#define OFF_RADW2 1761280    // 1536 x   64
#define WTOT      1859584
static __device__ __half g_w[WTOT];

// ---------------- helpers ----------------
__device__ __forceinline__ float sigmoidf_(float x) { return 1.0f / (1.0f + expf(-x)); }
__device__ __forceinline__ float siluf_(float x)    { return x / (1.0f + expf(-x)); }
__device__ __forceinline__ float envf_(float dist) {
    float d = dist * (1.0f / 6.0f);
    float d2 = d * d;
    float d5 = d2 * d2 * d;
    return (d < 1.0f) ? (1.0f - 21.0f * d5 + 35.0f * d5 * d - 15.0f * d5 * d2) : 0.0f;
}

__device__ __forceinline__ uint32_t smem_u32(const void* p) {
    uint32_t a;
    asm("{ .reg .u64 t; cvta.to.shared.u64 t, %1; cvt.u32.u64 %0, t; }" : "=r"(a) : "l"(p));
    return a;
}
__device__ __forceinline__ void cpa16(uint32_t dst, const void* src) {
    asm volatile("cp.async.cg.shared.global [%0], [%1], 16;" :: "r"(dst), "l"(src));
}
__device__ __forceinline__ void ldsm4(uint32_t* r, uint32_t addr) {
    asm volatile("ldmatrix.sync.aligned.m8n8.x4.shared.b16 {%0,%1,%2,%3}, [%4];"
        : "=r"(r[0]), "=r"(r[1]), "=r"(r[2]), "=r"(r[3]) : "r"(addr));
}
__device__ __forceinline__ void mma16816(float* d, const uint32_t* a, const uint32_t* b) {
    asm volatile(
        "mma.sync.aligned.m16n8k16.row.col.f32.f16.f16.f32 "
        "{%0,%1,%2,%3}, {%4,%5,%6,%7}, {%8,%9}, {%0,%1,%2,%3};"
        : "+f"(d[0]), "+f"(d[1]), "+f"(d[2]), "+f"(d[3])
        : "r"(a[0]), "r"(a[1]), "r"(a[2]), "r"(a[3]), "r"(b[0]), "r"(b[1]));
}
__device__ __forceinline__ uint32_t pack2h(float a, float b) {
    __half2 h = __floats2half2_rn(a, b);
    return *(uint32_t*)&h;
}
__device__ __forceinline__ void red4(float* p, float a, float b, float c, float d) {
    asm volatile("red.global.v4.f32.add [%0], {%1, %2, %3, %4};"
        :: "l"(p), "f"(a), "f"(b), "f"(c), "f"(d) : "memory");
}

// ---------------- zero fill ----------------
__global__ void zero_kernel(float* p, int n) {
    int i = blockIdx.x * blockDim.x + threadIdx.x;
    if (i < n) p[i] = 0.0f;
}

// ---------------- pad rows [NE, EPAD) of fp16 A buffers ----------------
__global__ void pad_kernel() {
    int i = blockIdx.x * 256 + threadIdx.x;
    __half z = __float2half(0.0f);
    if (i < 64 * MSG1_W) {
        g_m1[(size_t)(NE + i / MSG1_W) * MSG1_W + (i % MSG1_W)] = z;
    }
    if (i < 64 * H1_W) {
        g_h1[(size_t)(NE + i / H1_W) * H1_W + (i % H1_W)] = z;
    }
    if (i < 64 * 64) {
        g_t64[(size_t)(NE + i / 64) * 64 + (i % 64)] = z;
    }
}

// ---------------- weight convert: all 7 matrices in one launch (single fp16) ----------------
__device__ __forceinline__ void cw_t(const float* __restrict__ W, int K, int N, int Npad,
                                     __half* w, int i) {
    if (i < Npad * K) {
        int n = i / K, k = i - n * K;
        float v = (n < N) ? W[(size_t)k * N + n] : 0.0f;
        w[i] = __float2half_rn(v);
    }
}
__device__ __forceinline__ void cw_c(const float* __restrict__ W, int K2, int halfc,
                                     __half* w, int i) {
    int Kc = 2 * K2, Nc = 2 * halfc;
    if (i < Nc * Kc) {
        int n = i / Kc, k = i - n * Kc;
        float v;
        if (k < K2)           v = W[(size_t)k * Nc + n];
        else if (n < halfc)   v = -W[(size_t)(k - K2) * Nc + halfc + n];
        else                  v = W[(size_t)(k - K2) * Nc + (n - halfc)];
        w[i] = __float2half_rn(v);
    }
}
// block ranges: [0,1600) c1fc0 | [1600,3648) c1m1 | [3648,4800) c1m2 |
// [4800,5280) c2fc0 | [5280,6304) c2m1 | [6304,6880) c2m2 | [6880,7264) radw2
#define CONVW_BLOCKS 7264
__global__ void convw_all(
    const float* __restrict__ c1_fc0_w, const float* __restrict__ c1_m1_w,
    const float* __restrict__ c1_m2_w,  const float* __restrict__ c2_fc0_w,
    const float* __restrict__ c2_m1_w,  const float* __restrict__ c2_m2_w,
    const float* __restrict__ rad_w2)
{
    int b = blockIdx.x;
    int t = threadIdx.x;
    if (b < 1600)      cw_t(c1_fc0_w, 640, 576, 640,  g_w + OFF_C1FC0, (b - 0)    * 256 + t);
    else if (b < 3648) cw_c(c1_m1_w,  512, 256,       g_w + OFF_C1M1C, (b - 1600) * 256 + t);
    else if (b < 4800) cw_c(c1_m2_w,  384, 192,       g_w + OFF_C1M2C, (b - 3648) * 256 + t);
    else if (b < 5280) cw_t(c2_fc0_w, 320, 320, 384,  g_w + OFF_C2FC0, (b - 4800) * 256 + t);
    else if (b < 6304) cw_c(c2_m1_w,  256, 256,       g_w + OFF_C2M1C, (b - 5280) * 256 + t);
    else if (b < 6880) cw_c(c2_m2_w,  192, 192,       g_w + OFF_C2M2C, (b - 6304) * 256 + t);
    else               cw_t(rad_w2,   64, 1536, 1536, g_w + OFF_RADW2, (b - 6880) * 256 + t);
}

// ---------------- SIMT fp32 GEMM (tiny radial layers only) ----------------
__global__ void __launch_bounds__(256) gemm64(
    const float* __restrict__ A, int lda,
    const float* __restrict__ W, int N, int K,
    const float* __restrict__ bias,
    float* __restrict__ C, int ldc)
{
    __shared__ __align__(16) float As[16][68];
    __shared__ __align__(16) float Bs[16][64];

    int tid = threadIdx.x;
    int tx = tid & 15, ty = tid >> 4;
    int m0 = blockIdx.y * 64, n0 = blockIdx.x * 64;
    int ar = tid >> 2, ac = (tid & 3) * 4;
    int wr = tid >> 4, wc = (tid & 15) * 4;
    const float* Ap = A + (size_t)(m0 + ar) * lda + ac;

    float acc[4][4];
#pragma unroll
    for (int i = 0; i < 4; i++)
#pragma unroll
        for (int j = 0; j < 4; j++) acc[i][j] = 0.0f;

    for (int k0 = 0; k0 < K; k0 += 16) {
        float4 av = *(const float4*)(Ap + k0);
        float4 bv = *(const float4*)(W + (size_t)(k0 + wr) * N + n0 + wc);
        As[ac + 0][ar] = av.x; As[ac + 1][ar] = av.y;
        As[ac + 2][ar] = av.z; As[ac + 3][ar] = av.w;
        *(float4*)&Bs[wr][wc] = bv;
        __syncthreads();
#pragma unroll
        for (int kk = 0; kk < 16; kk++) {
            float4 a = *(const float4*)&As[kk][ty * 4];
            float4 b = *(const float4*)&Bs[kk][tx * 4];
            float av_[4] = {a.x, a.y, a.z, a.w};
            float bv_[4] = {b.x, b.y, b.z, b.w};
#pragma unroll
            for (int i = 0; i < 4; i++)
#pragma unroll
                for (int j = 0; j < 4; j++) acc[i][j] += av_[i] * bv_[j];
        }
        __syncthreads();
    }
    float bb[4] = {0.f, 0.f, 0.f, 0.f};
    if (bias) {
#pragma unroll
        for (int j = 0; j < 4; j++) bb[j] = bias[n0 + tx * 4 + j];
    }
#pragma unroll
    for (int i = 0; i < 4; i++) {
        float* Cp = C + (size_t)(m0 + ty * 4 + i) * ldc + n0 + tx * 4;
#pragma unroll
        for (int j = 0; j < 4; j++) Cp[j] = acc[i][j] + bb[j];
    }
}

// ---------------- fp16 single-pass mma.sync GEMM, BM=128 BN=128 BK=32, 3-stage ----------------
// C = A @ W^T ; A and W single fp16, fp32 accumulate.
#define STG_BYTES 20480     // A 128*40*2 + B 128*40*2
#define NSTAGE 3
#define SMEM_MMA  (NSTAGE * STG_BYTES)

__global__ void __launch_bounds__(256) mma_gemm(
    const __half* __restrict__ A, int lda, int col0,
    const __half* __restrict__ W,
    int K, int mode, int mtype, int Nreal,
    const float* __restrict__ bias,
    const float* __restrict__ edge_distance,
    const float* __restrict__ gsrc,           // t576 for gating
    float* __restrict__ Cf, int ldc,
    __half* __restrict__ Ch)
{
    extern __shared__ __align__(128) char smem[];
    uint32_t sb = smem_u32(smem);
    int tid = threadIdx.x, lane = tid & 31, wid = tid >> 5;
    int wrow = wid & 1, wcol = wid >> 1;
    int m0 = blockIdx.y << 7, n0 = blockIdx.x << 7;
    int nch = K >> 5;

    float acc[4][4][4];
#pragma unroll
    for (int mt = 0; mt < 4; mt++)
#pragma unroll
        for (int nt = 0; nt < 4; nt++)
#pragma unroll
            for (int j = 0; j < 4; j++) acc[mt][nt][j] = 0.0f;

    auto load = [&](int s, int c) {
        int kc = c << 5;
        uint32_t so = sb + (uint32_t)s * STG_BYTES;
#pragma unroll
        for (int ii = 0; ii < 2; ii++) {
            int i = tid + ii * 256;                 // 0..511
            int row = i >> 2, ch = (i & 3) << 3;
            size_t gA = (size_t)(m0 + row) * lda + col0 + kc + ch;
            cpa16(so + (uint32_t)(row * 40 + ch) * 2, A + gA);
            size_t gB = (size_t)(n0 + row) * K + kc + ch;
            cpa16(so + 10240 + (uint32_t)(row * 40 + ch) * 2, W + gB);
        }
        asm volatile("cp.async.commit_group;" ::: "memory");
    };

    load(0, 0);
    if (nch > 1) load(1, 1);

    for (int c = 0; c < nch; c++) {
        int s = c % NSTAGE;
        if (c + 1 < nch) asm volatile("cp.async.wait_group 1;" ::: "memory");
        else             asm volatile("cp.async.wait_group 0;" ::: "memory");
        __syncthreads();
        if (c + 2 < nch) load((c + 2) % NSTAGE, c + 2);

        uint32_t so = sb + (uint32_t)s * STG_BYTES;
#pragma unroll
        for (int ks = 0; ks < 2; ks++) {
            uint32_t ah[4][4], bh[2][4];
            int arow = wrow * 64 + (lane & 15);
            uint32_t aoff = so + (uint32_t)(arow * 40 + ks * 16 + ((lane >> 4) << 3)) * 2;
#pragma unroll
            for (int mt = 0; mt < 4; mt++)
                ldsm4(ah[mt], aoff + mt * 16 * 80);
            int nrow = wcol * 32 + (lane & 7) + ((lane >> 4) << 3);
            uint32_t boff = so + 10240 +
                            (uint32_t)(nrow * 40 + ks * 16 + (((lane >> 3) & 1) << 3)) * 2;
            ldsm4(bh[0], boff);
            ldsm4(bh[1], boff + 16 * 80);
#pragma unroll
            for (int mt = 0; mt < 4; mt++)
#pragma unroll
                for (int nt = 0; nt < 4; nt++)
                    mma16816(acc[mt][nt], ah[mt], &bh[nt >> 1][(nt & 1) * 2]);
        }
    }

    // ---------------- fused epilogue (vectorized stores) ----------------
    int mbase = m0 + wrow * 64;
    int ncb = n0 + wcol * 32 + (lane & 3) * 2;
#pragma unroll
    for (int mt = 0; mt < 4; mt++) {
#pragma unroll
        for (int half = 0; half < 2; half++) {
            int row = mbase + mt * 16 + (lane >> 2) + half * 8;
            if (row >= NE) continue;
            float env = 0.0f;
            if (mode == 2) env = envf_(edge_distance[row]);
#pragma unroll
            for (int nt = 0; nt < 4; nt++) {
                int ccol = ncb + nt * 8;
                float v0 = acc[mt][nt][half * 2 + 0];
                float v1 = acc[mt][nt][half * 2 + 1];
                if (mode == 0) {
                    if (ccol < Nreal) {
                        float b0 = 0.f, b1 = 0.f;
                        if (bias) { b0 = bias[ccol]; b1 = bias[ccol + 1]; }
                        float2* Cp = (float2*)(Cf + (size_t)row * ldc + ccol);
                        *Cp = make_float2(v0 + b0, v1 + b1);
                    }
                } else if (mode == 1) {
                    int j = ccol >> 6, cc = ccol & 63;
                    int hrow = ((mtype == 1) ? 5 : 13) + j;
                    int lp = (mtype == 1) ? (j & 3) : ((j < 3) ? j + 1 : j - 2);
                    float2 gv = *(const float2*)(gsrc + (size_t)row * 576 + 320 + lp * 64 + cc);
                    size_t o = (size_t)row * H1_W + hrow * 64 + cc;
                    *(uint32_t*)(Ch + o) = pack2h(v0 * sigmoidf_(gv.x), v1 * sigmoidf_(gv.y));
                } else {
                    int off;
                    float b0 = 0.f, b1 = 0.f;
                    if (mtype == 0) {
                        if (ccol >= Nreal) continue;
                        off = ccol;
                        if (bias) { b0 = bias[ccol]; b1 = bias[ccol + 1]; }
                    } else {
                        int j = ccol >> 6, cc = ccol & 63;
                        int hrow = ((mtype == 1) ? 5 : 13) + j;
                        off = hrow * 64 + cc;
                    }
                    size_t o = (size_t)row * H1_W + off;
                    *(uint32_t*)(Ch + o) = pack2h((v0 + b0) * env, (v1 + b1) * env);
                }
            }
        }
    }
}

// ---------------- LayerNorm + SiLU, 4 edges/block ----------------
__global__ void __launch_bounds__(256) lnsilu_kernel(
    float* __restrict__ h,
    const float* __restrict__ g,
    const float* __restrict__ b,
    __half* __restrict__ ho)
{
    int sub = threadIdx.x >> 6;
    int t = threadIdx.x & 63;
    int e = blockIdx.x * 4 + sub;
    float v = h[(size_t)e * 64 + t];

    __shared__ float red[4][4];
    float s = v;
#pragma unroll
    for (int o = 16; o > 0; o >>= 1) s += __shfl_xor_sync(0xffffffffu, s, o);
    if ((t & 31) == 0) red[sub][t >> 5] = s;
    __syncthreads();
    float mu = (red[sub][0] + red[sub][1]) * (1.0f / 64.0f);

    float d = v - mu;
    float s2 = d * d;
#pragma unroll
    for (int o = 16; o > 0; o >>= 1) s2 += __shfl_xor_sync(0xffffffffu, s2, o);
    if ((t & 31) == 0) red[sub][2 + (t >> 5)] = s2;
    __syncthreads();
    float var = (red[sub][2] + red[sub][3]) * (1.0f / 64.0f);

    float y = siluf_(d * rsqrtf(var + 1e-5f) * g[t] + b[t]);
    if (ho) ho[(size_t)e * 64 + t] = __float2half_rn(y);
    else    h[(size_t)e * 64 + t] = y;
}

// ---------------- wigner forward: register-blocked, fp16 out ----------------
__global__ void __launch_bounds__(128) wig_fwd2(
    const float* __restrict__ x,
    const int* __restrict__ edge_index,
    const float* __restrict__ wigner,
    const float* __restrict__ rad,
    __half* __restrict__ m1)
{
    int e = blockIdx.x;
    int tid = threadIdx.x;
    int w = tid >> 5, lane = tid & 31;
    __shared__ float sw[500];
    __shared__ __align__(16) float sx[NFULL * 128];

    int src = edge_index[e];
    int dst = edge_index[NE + e];
    const float* wp = wigner + (size_t)e * (NM * NFULL);
    for (int i = tid; i < NM * NFULL; i += 128) sw[i] = wp[i];

    const float4* xs = (const float4*)(x + (size_t)src * (NFULL * 64));
    const float4* xd = (const float4*)(x + (size_t)dst * (NFULL * 64));
    for (int i = tid; i < NFULL * 16; i += 128) {
        int k = i >> 4, c = (i & 15) << 2;
        *(float4*)&sx[k * 128 + c]      = xs[i];
        *(float4*)&sx[k * 128 + 64 + c] = xd[i];
    }
    __syncthreads();

    int r0 = w * 5;
    int nr = (w == 3) ? 4 : 5;
    int f0 = lane * 4;
    float acc[5][4];
#pragma unroll
    for (int i = 0; i < 5; i++)
#pragma unroll
        for (int j = 0; j < 4; j++) acc[i][j] = 0.0f;

#pragma unroll
    for (int k = 0; k < NFULL; k++) {
        float4 xv = *(const float4*)&sx[k * 128 + f0];
#pragma unroll
        for (int rr = 0; rr < 5; rr++) {
            float wv = sw[(r0 + rr) * NFULL + k];
            acc[rr][0] += wv * xv.x;
            acc[rr][1] += wv * xv.y;
            acc[rr][2] += wv * xv.z;
            acc[rr][3] += wv * xv.w;
        }
    }

    const float* rp = rad + (size_t)e * RAD_W;
    for (int rr = 0; rr < nr; rr++) {
        int r = r0 + rr;
        int sbase;
        if (r < 5)       sbase = r * 128;
        else if (r < 13) sbase = 640  + ((r - 5) & 3) * 128;
        else             sbase = 1152 + ((r - 13) % 3) * 128;
        size_t o = (size_t)e * MSG1_W + r * 128 + f0;
        float4 rv = *(const float4*)(rp + sbase + f0);
        uint2 pk;
        pk.x = pack2h(acc[rr][0] * rv.x, acc[rr][1] * rv.y);
        pk.y = pack2h(acc[rr][2] * rv.z, acc[rr][3] * rv.w);
        *(uint2*)(m1 + o) = pk;
    }
}

// ---------------- assemble conv1 rows 0..4 (silu + gated scalars) ----------------
__global__ void __launch_bounds__(128) assemble1a_kernel(
    const float* __restrict__ t576,
    __half* __restrict__ h1)
{
    int e = blockIdx.x;
    int tid = threadIdx.x;
    if (tid >= 80) return;
    const float* T = t576 + (size_t)e * 576;
    int o = tid * 4;
    int r = o >> 6, c = o & 63;
    float4 v = *(const float4*)(T + o);
    if (r == 0) {
        v.x = siluf_(v.x); v.y = siluf_(v.y); v.z = siluf_(v.z); v.w = siluf_(v.w);
    } else {
        float4 gv = *(const float4*)(T + 320 + (r - 1) * 64 + c);
        v.x *= sigmoidf_(gv.x); v.y *= sigmoidf_(gv.y);
        v.z *= sigmoidf_(gv.z); v.w *= sigmoidf_(gv.w);
    }
    uint2 pk;
    pk.x = pack2h(v.x, v.y);
    pk.y = pack2h(v.z, v.w);
    *(uint2*)(h1 + (size_t)e * H1_W + o) = pk;
}

// ---------------- wigner inverse + vector red scatter ----------------
__global__ void __launch_bounds__(256) wig_inv_kernel(
    const float* __restrict__ wigner_inv,
    const __half* __restrict__ msg2h,
    const int* __restrict__ edge_index,
    float* __restrict__ out)
{
    int e = blockIdx.x;
    int tid = threadIdx.x;
    __shared__ float sw[NFULL * NM];
    __shared__ __align__(16) float sm[NM * 64];

    const float* wp = wigner_inv + (size_t)e * (NFULL * NM);
    for (int i = tid; i < NFULL * NM; i += 256) sw[i] = wp[i];
    const __half2* mp = (const __half2*)(msg2h + (size_t)e * H1_W);
    for (int i = tid; i < H1_W / 2; i += 256) {
        float2 f = __half22float2(mp[i]);
        sm[2 * i] = f.x;
        sm[2 * i + 1] = f.y;
    }
    __syncthreads();

    int dst = edge_index[NE + e];
    float* op = out + (size_t)dst * (NFULL * 64);
    for (int o4 = tid * 4; o4 < NFULL * 64; o4 += 1024) {
        int j = o4 >> 6, c = o4 & 63;
        const float* wr = &sw[j * NM];
        float s0 = 0.f, s1 = 0.f, s2 = 0.f, s3 = 0.f;
#pragma unroll
        for (int r = 0; r < NM; r++) {
            float w = wr[r];
            const float* smr = &sm[r * 64 + c];
            s0 += w * smr[0];
            s1 += w * smr[1];
            s2 += w * smr[2];
            s3 += w * smr[3];
        }
        red4(op + o4, s0, s1, s2, s3);
    }
}

// ---------------- host side ----------------
static float* symaddrf(const void* sym) {
    void* p = nullptr;
    cudaGetSymbolAddress(&p, sym);
    return (float*)p;
}
static __half* symaddrh(const void* sym) {
    void* p = nullptr;
    cudaGetSymbolAddress(&p, sym);
    return (__half*)p;
}

extern "C" void kernel_launch(void* const* d_in, const int* in_sizes, int n_in,
                              void* d_out, int out_size)
{
    const float* x             = (const float*)d_in[0];
    const float* x_edge        = (const float*)d_in[1];
    const float* edge_distance = (const float*)d_in[2];
    const int*   edge_index    = (const int*)  d_in[3];
    const float* wigner        = (const float*)d_in[4];
    const float* wigner_inv    = (const float*)d_in[5];
    const float* rad_w0        = (const float*)d_in[6];
    const float* rad_b0        = (const float*)d_in[7];
    const float* rad_ln0_g     = (const float*)d_in[8];
    const float* rad_ln0_b     = (const float*)d_in[9];
    const float* rad_w1        = (const float*)d_in[10];
    const float* rad_b1        = (const float*)d_in[11];
    const float* rad_ln1_g     = (const float*)d_in[12];
    const float* rad_ln1_b     = (const float*)d_in[13];
    const float* rad_w2        = (const float*)d_in[14];
    const float* rad_b2        = (const float*)d_in[15];
    const float* c1_fc0_w      = (const float*)d_in[16];
    const float* c1_fc0_b      = (const float*)d_in[17];
    const float* c1_m1_w       = (const float*)d_in[18];
    const float* c1_m2_w       = (const float*)d_in[19];
    const float* c2_fc0_w      = (const float*)d_in[20];
    const float* c2_fc0_b      = (const float*)d_in[21];
    const float* c2_m1_w       = (const float*)d_in[22];
    const float* c2_m2_w       = (const float*)d_in[23];
    float* out = (float*)d_out;

    static int smem_set = 0;
    if (!smem_set) {
        cudaFuncSetAttribute(mma_gemm, cudaFuncAttributeMaxDynamicSharedMemorySize, SMEM_MMA);
        smem_set = 1;
    }

    float* p_t64a  = symaddrf(g_t64a);
    float* p_t64b  = symaddrf(g_t64b);
    float* p_rad   = symaddrf(g_rad);
    float* p_t576  = symaddrf(g_t576);
    __half* p_m1    = symaddrh(g_m1);
    __half* p_h1    = symaddrh(g_h1);
    __half* p_t64   = symaddrh(g_t64);
    __half* p_msg2h = symaddrh(g_msg2h);
    __half* p_w     = symaddrh(g_w);

    // 0. zero output, pad rows, build weights
    zero_kernel<<<(OUT_ELEMS + 255) / 256, 256>>>(out, OUT_ELEMS);
    pad_kernel<<<(64 * MSG1_W + 255) / 256, 256>>>();
    convw_all<<<CONVW_BLOCKS, 256>>>(c1_fc0_w, c1_m1_w, c1_m2_w,
                                     c2_fc0_w, c2_m1_w, c2_m2_w, rad_w2);

    // 1. radial MLP (layers 0/1 SIMT, layer 2 tensor)
    {
        dim3 grid(1, NE / 64);
        gemm64<<<grid, 256>>>(x_edge, 128, rad_w0, 64, 128, rad_b0, p_t64a, 64);
        lnsilu_kernel<<<NE / 4, 256>>>(p_t64a, rad_ln0_g, rad_ln0_b, nullptr);
        gemm64<<<grid, 256>>>(p_t64a, 64, rad_w1, 64, 64, rad_b1, p_t64b, 64);
        lnsilu_kernel<<<NE / 4, 256>>>(p_t64b, rad_ln1_g, rad_ln1_b, p_t64);
    }
    mma_gemm<<<dim3(12, MTILES), 256, SMEM_MMA>>>(
        p_t64, 64, 0, p_w + OFF_RADW2, 64,
        0, 0, 1536, rad_b2, nullptr, nullptr, p_rad, RAD_W, nullptr);

    // 2. gather + wigner rotate + radial prescale -> fp16
    wig_fwd2<<<NE, 128>>>(x, edge_index, wigner, p_rad, p_m1);

    // 3. conv1: fc0 -> t576 (fp32), then gated complex m-convs -> h1 (fp16)
    mma_gemm<<<dim3(5, MTILES), 256, SMEM_MMA>>>(
        p_m1, MSG1_W, 0, p_w + OFF_C1FC0, 640,
        0, 0, 576, c1_fc0_b, nullptr, nullptr, p_t576, 576, nullptr);
    assemble1a_kernel<<<NE, 128>>>(p_t576, p_h1);
    mma_gemm<<<dim3(4, MTILES), 256, SMEM_MMA>>>(
        p_m1, MSG1_W, 640, p_w + OFF_C1M1C, 1024,
        1, 1, 512, nullptr, nullptr, p_t576, nullptr, 0, p_h1);
    mma_gemm<<<dim3(3, MTILES), 256, SMEM_MMA>>>(
        p_m1, MSG1_W, 1664, p_w + OFF_C1M2C, 768,
        1, 2, 384, nullptr, nullptr, p_t576, nullptr, 0, p_h1);

    // 4. conv2: envelope fused, write msg2h (fp16) directly
    mma_gemm<<<dim3(3, MTILES), 256, SMEM_MMA>>>(
        p_h1, H1_W, 0, p_w + OFF_C2FC0, 320,
        2, 0, 320, c2_fc0_b, edge_distance, nullptr, nullptr, 0, p_msg2h);
    mma_gemm<<<dim3(4, MTILES), 256, SMEM_MMA>>>(
        p_h1, H1_W, 320, p_w + OFF_C2M1C, 512,
        2, 1, 512, nullptr, edge_distance, nullptr, nullptr, 0, p_msg2h);
    mma_gemm<<<dim3(3, MTILES), 256, SMEM_MMA>>>(
        p_h1, H1_W, 832, p_w + OFF_C2M2C, 384,
        2, 2, 384, nullptr, edge_distance, nullptr, nullptr, 0, p_msg2h);

    // 5. inverse wigner + vector-red scatter
    wig_inv_kernel<<<NE, 256>>>(wigner_inv, p_msg2h, edge_index, out);
}